// round 16
// baseline (speedup 1.0000x reference)
#include <cuda_runtime.h>
#include <cuda_fp16.h>
#include <cstdint>

#define BTS   16384      // B*T*S
#define SEQ   1024
#define DM    256
#define NBT   16
#define NH    8
#define DKH   32

// Scratch (device globals — no allocation allowed)
__device__ __half g_qh [BTS * DM];
__device__ __half g_kh [BTS * DM];
__device__ __half g_vh [BTS * DM];
__device__ __half g_xh [BTS * DM];
__device__ __half g_whq[DM * DM];
__device__ __half g_whk[DM * DM];
__device__ __half g_whv[DM * DM];
__device__ __half g_who[DM * DM];
__device__ float  g_vpart[NBT * 8 * DM];
__device__ __half g_meanh[NBT * DM];

__device__ __forceinline__ uint32_t smem_u32(const void* p) {
    return (uint32_t)__cvta_generic_to_shared(p);
}

#define LDMX4(r0,r1,r2,r3,addr) \
    asm volatile("ldmatrix.sync.aligned.m8n8.x4.shared.b16 {%0,%1,%2,%3}, [%4];" \
        : "=r"(r0),"=r"(r1),"=r"(r2),"=r"(r3) : "r"(addr))

#define LDMX4T(r0,r1,r2,r3,addr) \
    asm volatile("ldmatrix.sync.aligned.m8n8.x4.trans.shared.b16 {%0,%1,%2,%3}, [%4];" \
        : "=r"(r0),"=r"(r1),"=r"(r2),"=r"(r3) : "r"(addr))

#define MMA16816(c0,c1,c2,c3,a0,a1,a2,a3,b0,b1) \
    asm volatile("mma.sync.aligned.m16n8k16.row.col.f32.f16.f16.f32 " \
        "{%0,%1,%2,%3}, {%4,%5,%6,%7}, {%8,%9}, {%0,%1,%2,%3};" \
        : "+f"(c0),"+f"(c1),"+f"(c2),"+f"(c3) \
        : "r"(a0),"r"(a1),"r"(a2),"r"(a3), "r"(b0),"r"(b1))

#define EX2F16X2(r) \
    asm volatile("ex2.approx.f16x2 %0, %0;" : "+r"(r))

#define CP16(dst, src) \
    asm volatile("cp.async.cg.shared.global [%0], [%1], 16;" :: "r"(dst), "l"(src))
#define CP_COMMIT()  asm volatile("cp.async.commit_group;")
#define CP_WAIT1()   asm volatile("cp.async.wait_group 1;")

// ---------------------------------------------------------------------------
// Weight fp32 -> fp16 (4 matrices 256x256)
// ---------------------------------------------------------------------------
__global__ void wconv_kernel(const float* __restrict__ s0, const float* __restrict__ s1,
                             const float* __restrict__ s2, const float* __restrict__ s3,
                             __half* __restrict__ d0, __half* __restrict__ d1,
                             __half* __restrict__ d2, __half* __restrict__ d3) {
    const float* s; __half* d;
    switch (blockIdx.y) {
        case 0: s = s0; d = d0; break;
        case 1: s = s1; d = d1; break;
        case 2: s = s2; d = d2; break;
        default: s = s3; d = d3; break;
    }
    const int i = (blockIdx.x * 256 + threadIdx.x) * 4;
    float4 v = *(const float4*)(s + i);
    *(__half2*)(d + i)     = __floats2half2_rn(v.x, v.y);
    *(__half2*)(d + i + 2) = __floats2half2_rn(v.z, v.w);
}

// ---------------------------------------------------------------------------
// QKV GEMM reading fp32 A directly (round-12/14 proven form).
// ---------------------------------------------------------------------------
#define PADG 40
#define STG_H (128 * PADG)

__global__ void __launch_bounds__(256, 2)
gemm_qkv_kernel(const float* __restrict__ A0, const float* __restrict__ A1,
                const float* __restrict__ A2,
                const __half* __restrict__ W0, const __half* __restrict__ W1,
                const __half* __restrict__ W2,
                const float* __restrict__ b0, const float* __restrict__ b1,
                const float* __restrict__ b2,
                __half* __restrict__ C0, __half* __restrict__ C1,
                __half* __restrict__ C2, float qscale) {
    __shared__ __half As[2 * STG_H];
    __shared__ __half Bs[3 * STG_H];

    const float* A; const __half* W; const float* bias; __half* C; float scale;
    switch (blockIdx.z) {
        case 0:  A = A0; W = W0; bias = b0; C = C0; scale = qscale; break;
        case 1:  A = A1; W = W1; bias = b1; C = C1; scale = 1.0f;   break;
        default: A = A2; W = W2; bias = b2; C = C2; scale = 1.0f;   break;
    }

    const int tid    = threadIdx.x;
    const int warp   = tid >> 5;
    const int lane   = tid & 31;
    const int warp_m = warp >> 2;
    const int warp_n = warp & 3;
    const int m0     = blockIdx.y * 128;
    const int n0     = blockIdx.x * 128;
    const int g      = lane >> 2;
    const int tg     = lane & 3;

    const int arow  = tid >> 1;
    const int acol  = (tid & 1) * 16;
    const float* Abase = A + (size_t)(m0 + arow) * DM + acol;

    uint4 areg[2];
    auto aload = [&](int k0) {
        #pragma unroll
        for (int i = 0; i < 2; i++) {
            float4 f0 = *(const float4*)(Abase + k0 + i * 8);
            float4 f1 = *(const float4*)(Abase + k0 + i * 8 + 4);
            __half2 h0 = __floats2half2_rn(f0.x, f0.y);
            __half2 h1 = __floats2half2_rn(f0.z, f0.w);
            __half2 h2 = __floats2half2_rn(f1.x, f1.y);
            __half2 h3 = __floats2half2_rn(f1.z, f1.w);
            areg[i].x = *(uint32_t*)&h0; areg[i].y = *(uint32_t*)&h1;
            areg[i].z = *(uint32_t*)&h2; areg[i].w = *(uint32_t*)&h3;
        }
    };
    auto asts = [&](int buf) {
        *(uint4*)&As[buf * STG_H + arow * PADG + acol]     = areg[0];
        *(uint4*)&As[buf * STG_H + arow * PADG + acol + 8] = areg[1];
    };
    auto bcopy = [&](int stg, int k0) {
        #pragma unroll
        for (int u = tid; u < 512; u += 256) {
            const int row = u >> 2, seg = u & 3;
            CP16(smem_u32(&Bs[stg * STG_H + row * PADG + seg * 8]),
                 W + (size_t)(n0 + row) * DM + k0 + seg * 8);
        }
    };

    float c[4][4][4] = {};

    aload(0);
    bcopy(0, 0);  CP_COMMIT();
    bcopy(1, 32); CP_COMMIT();
    asts(0);
    aload(32);
    CP_WAIT1();
    __syncthreads();

    #pragma unroll
    for (int step = 0; step < 8; step++) {
        const int sa = step & 1;
        const int sb = step % 3;

        if (step < 7) asts((step + 1) & 1);
        if (step < 6) aload((step + 2) * 32);
        if (step + 2 < 8) bcopy((step + 2) % 3, (step + 2) * 32);
        CP_COMMIT();

        uint32_t bb[4][4];
        #pragma unroll
        for (int ni = 0; ni < 4; ni++) {
            const int lrow = warp_n * 32 + ni * 8 + (lane & 7);
            const int lcol = (lane >> 3) * 8;
            uint32_t addr = smem_u32(&Bs[sb * STG_H + lrow * PADG + lcol]);
            LDMX4(bb[ni][0], bb[ni][1], bb[ni][2], bb[ni][3], addr);
        }

        #pragma unroll
        for (int kh = 0; kh < 2; kh++) {
            uint32_t aa[4][4];
            const int lcol = kh * 16 + ((lane >> 4) & 1) * 8;
            #pragma unroll
            for (int mi = 0; mi < 4; mi++) {
                const int lrow = warp_m * 64 + mi * 16 + (lane & 7) + ((lane >> 3) & 1) * 8;
                uint32_t addr = smem_u32(&As[sa * STG_H + lrow * PADG + lcol]);
                LDMX4(aa[mi][0], aa[mi][1], aa[mi][2], aa[mi][3], addr);
            }
            #pragma unroll
            for (int mi = 0; mi < 4; mi++)
                #pragma unroll
                for (int ni = 0; ni < 4; ni++)
                    MMA16816(c[mi][ni][0], c[mi][ni][1], c[mi][ni][2], c[mi][ni][3],
                             aa[mi][0], aa[mi][1], aa[mi][2], aa[mi][3],
                             bb[ni][kh * 2], bb[ni][kh * 2 + 1]);
        }

        CP_WAIT1();
        __syncthreads();
    }

    #pragma unroll
    for (int mi = 0; mi < 4; mi++) {
        const int row0 = m0 + warp_m * 64 + mi * 16 + g;
        const int row1 = row0 + 8;
        #pragma unroll
        for (int ni = 0; ni < 4; ni++) {
            const int col = n0 + warp_n * 32 + ni * 8 + 2 * tg;
            const float bb0 = bias[col], bb1 = bias[col + 1];
            *(__half2*)(C + (size_t)row0 * DM + col) =
                __floats2half2_rn((c[mi][ni][0] + bb0) * scale, (c[mi][ni][1] + bb1) * scale);
            *(__half2*)(C + (size_t)row1 * DM + col) =
                __floats2half2_rn((c[mi][ni][2] + bb0) * scale, (c[mi][ni][3] + bb1) * scale);
        }
    }
}

// ---------------------------------------------------------------------------
// Output GEMM (fp16 A, fp16 W, fp32 out): 3-buffer cp.async ring.
// Mask-aware A copy: rows with seq >= len source the fp16 mean(V) vector, so
// invalid rows come out of the GEMM as meanV*Wo + bo directly (no fill pass).
// ---------------------------------------------------------------------------
__global__ void __launch_bounds__(256, 2)
gemm_out_kernel(const __half* __restrict__ A, const __half* __restrict__ W,
                const float* __restrict__ bias, float* __restrict__ C,
                const int* __restrict__ mask, const __half* __restrict__ Mh) {
    __shared__ __half As[3 * STG_H];
    __shared__ __half Bs[3 * STG_H];

    const int tid    = threadIdx.x;
    const int warp   = tid >> 5;
    const int lane   = tid & 31;
    const int warp_m = warp >> 2;
    const int warp_n = warp & 3;
    const int m0     = blockIdx.y * 128;
    const int n0     = blockIdx.x * 128;
    const int g      = lane >> 2;
    const int tg     = lane & 3;

    const int bt   = m0 >> 10;            // 128 rows always within one bt
    const int len  = mask[bt];
    const int seq0 = m0 & 1023;
    const __half* Mrow = Mh + (size_t)bt * DM;

    auto stage_copy = [&](int s, int k0) {
        #pragma unroll
        for (int u = tid; u < 512; u += 256) {
            const int row = u >> 2, seg = u & 3;
            const __half* srcA = (seq0 + row < len)
                ? A + (size_t)(m0 + row) * DM + k0 + seg * 8
                : Mrow + k0 + seg * 8;
            CP16(smem_u32(&As[s * STG_H + row * PADG + seg * 8]), srcA);
            CP16(smem_u32(&Bs[s * STG_H + row * PADG + seg * 8]),
                 W + (size_t)(n0 + row) * DM + k0 + seg * 8);
        }
        CP_COMMIT();
    };

    float c[4][4][4] = {};
    stage_copy(0, 0);
    stage_copy(1, 32);

    #pragma unroll
    for (int step = 0; step < 8; step++) {
        const int s = step % 3;
        CP_WAIT1();
        __syncthreads();

        const int kn = (step + 2 < 8) ? (step + 2) * 32 : 224;
        stage_copy((step + 2) % 3, kn);

        uint32_t bb[4][4];
        #pragma unroll
        for (int ni = 0; ni < 4; ni++) {
            const int lrow = warp_n * 32 + ni * 8 + (lane & 7);
            const int lcol = (lane >> 3) * 8;
            uint32_t addr = smem_u32(&Bs[s * STG_H + lrow * PADG + lcol]);
            LDMX4(bb[ni][0], bb[ni][1], bb[ni][2], bb[ni][3], addr);
        }
        #pragma unroll
        for (int kh = 0; kh < 2; kh++) {
            uint32_t aa[4][4];
            const int lcol = kh * 16 + ((lane >> 4) & 1) * 8;
            #pragma unroll
            for (int mi = 0; mi < 4; mi++) {
                const int lrow = warp_m * 64 + mi * 16 + (lane & 7) + ((lane >> 3) & 1) * 8;
                uint32_t addr = smem_u32(&As[s * STG_H + lrow * PADG + lcol]);
                LDMX4(aa[mi][0], aa[mi][1], aa[mi][2], aa[mi][3], addr);
            }
            #pragma unroll
            for (int mi = 0; mi < 4; mi++)
                #pragma unroll
                for (int ni = 0; ni < 4; ni++)
                    MMA16816(c[mi][ni][0], c[mi][ni][1], c[mi][ni][2], c[mi][ni][3],
                             aa[mi][0], aa[mi][1], aa[mi][2], aa[mi][3],
                             bb[ni][kh * 2], bb[ni][kh * 2 + 1]);
        }
    }

    #pragma unroll
    for (int mi = 0; mi < 4; mi++) {
        const int row0 = m0 + warp_m * 64 + mi * 16 + g;
        const int row1 = row0 + 8;
        #pragma unroll
        for (int ni = 0; ni < 4; ni++) {
            const int col = n0 + warp_n * 32 + ni * 8 + 2 * tg;
            const float b0 = bias[col], b1 = bias[col + 1];
            *(float2*)(C + (size_t)row0 * DM + col) = make_float2(c[mi][ni][0] + b0, c[mi][ni][1] + b1);
            *(float2*)(C + (size_t)row1 * DM + col) = make_float2(c[mi][ni][2] + b0, c[mi][ni][3] + b1);
        }
    }
}

// ---------------------------------------------------------------------------
// Flash attention (round-14 64-key-tile version) FUSED with V partial sums.
// ---------------------------------------------------------------------------
#define PAD 40
#define KV_STG (64 * PAD)

__global__ void __launch_bounds__(256, 3)
attn_vmean_kernel(const __half* __restrict__ Qh,
                  const __half* __restrict__ Kh,
                  const __half* __restrict__ Vh,
                  const int*    __restrict__ mask,
                  __half* __restrict__ XO,
                  float* __restrict__ vpart) {
    __shared__ __half Qs[128 * PAD];
    __shared__ __half Ks[3 * KV_STG];
    __shared__ __half Vs[3 * KV_STG];

    const int bt = blockIdx.z;

    if (blockIdx.y == NH) {
        const int seg = blockIdx.x;
        const int d   = threadIdx.x;
        const size_t b0 = (size_t)bt * SEQ * DM;
        float sum = 0.f;
        const int s0 = seg * 128;
        #pragma unroll 4
        for (int s = s0; s < s0 + 128; s++)
            sum += __half2float(Vh[b0 + (size_t)s * DM + d]);
        vpart[(bt * 8 + seg) * DM + d] = sum;
        return;
    }

    const int h   = blockIdx.y;
    const int r0  = blockIdx.x * 128;
    const int len = mask[bt];
    if (r0 >= len) return;

    const int tid  = threadIdx.x;
    const int warp = tid >> 5;
    const int lane = tid & 31;
    const int g    = lane >> 2;
    const int tg   = lane & 3;

    const size_t base = (size_t)bt * SEQ * DM + (size_t)h * DKH;

    const int crow = tid >> 2, cseg = tid & 3;
    auto copy_kv = [&](int stg, int t0) {
        const size_t src = base + (size_t)(t0 + crow) * DM + cseg * 8;
        CP16(smem_u32(&Ks[stg * KV_STG + crow * PAD + cseg * 8]), Kh + src);
        CP16(smem_u32(&Vs[stg * KV_STG + crow * PAD + cseg * 8]), Vh + src);
        CP_COMMIT();
    };

    const int ntile = (len + 63) >> 6;
    copy_kv(0, 0);
    copy_kv(1, (ntile > 1) ? 64 : 0);

    #pragma unroll
    for (int u = tid; u < 512; u += 256) {
        int row = u >> 2, ch = u & 3;
        *(uint4*)&Qs[row * PAD + ch * 8] =
            *(const uint4*)(Qh + base + (size_t)(r0 + row) * DM + ch * 8);
    }
    __syncthreads();

    uint32_t aq[2][4];
    {
        const int lrow = 16 * warp + (lane & 7) + ((lane >> 3) & 1) * 8;
        #pragma unroll
        for (int kh = 0; kh < 2; kh++) {
            const int lcol = kh * 16 + ((lane >> 4) & 1) * 8;
            uint32_t addr = smem_u32(&Qs[lrow * PAD + lcol]);
            LDMX4(aq[kh][0], aq[kh][1], aq[kh][2], aq[kh][3], addr);
        }
    }

    const uint32_t ONES2 = 0x3C003C00u;
    float ol[4] = {};
    float o[4][4] = {};

    for (int i = 0; i < ntile; i++) {
        const int s  = i % 3;
        const int t0 = i * 64;
        CP_WAIT1();
        __syncthreads();

        int tn = (i + 2) * 64;
        if (tn > SEQ - 64) tn = SEQ - 64;
        copy_kv((i + 2) % 3, tn);

        #pragma unroll
        for (int cc = 0; cc < 2; cc++) {
            float c[4][4];
            #pragma unroll
            for (int n = 0; n < 4; n++) { c[n][0]=0.f; c[n][1]=0.f; c[n][2]=0.f; c[n][3]=0.f; }

            #pragma unroll
            for (int n = 0; n < 4; n++) {
                uint32_t bk0, bk1, bk2, bk3;
                const int lrow = cc * 32 + n * 8 + (lane & 7);
                const int lcol = (lane >> 3) * 8;
                uint32_t addr = smem_u32(&Ks[s * KV_STG + lrow * PAD + lcol]);
                LDMX4(bk0, bk1, bk2, bk3, addr);
                MMA16816(c[n][0], c[n][1], c[n][2], c[n][3],
                         aq[0][0], aq[0][1], aq[0][2], aq[0][3], bk0, bk1);
                MMA16816(c[n][0], c[n][1], c[n][2], c[n][3],
                         aq[1][0], aq[1][1], aq[1][2], aq[1][3], bk2, bk3);
            }

            if (t0 + cc * 32 + 32 > len) {
                #pragma unroll
                for (int n = 0; n < 4; n++) {
                    const int col0 = t0 + cc * 32 + n * 8 + 2 * tg;
                    if (col0     >= len) { c[n][0] = -1e10f; c[n][2] = -1e10f; }
                    if (col0 + 1 >= len) { c[n][1] = -1e10f; c[n][3] = -1e10f; }
                }
            }

            uint32_t ap[2][4];
            #pragma unroll
            for (int kk = 0; kk < 2; kk++) {
                __half2 t;
                t = __floats2half2_rn(c[2*kk  ][0], c[2*kk  ][1]); ap[kk][0] = *(uint32_t*)&t;
                t = __floats2half2_rn(c[2*kk  ][2], c[2*kk  ][3]); ap[kk][1] = *(uint32_t*)&t;
                t = __floats2half2_rn(c[2*kk+1][0], c[2*kk+1][1]); ap[kk][2] = *(uint32_t*)&t;
                t = __floats2half2_rn(c[2*kk+1][2], c[2*kk+1][3]); ap[kk][3] = *(uint32_t*)&t;
                EX2F16X2(ap[kk][0]); EX2F16X2(ap[kk][1]);
                EX2F16X2(ap[kk][2]); EX2F16X2(ap[kk][3]);
            }

            #pragma unroll
            for (int kk = 0; kk < 2; kk++)
                MMA16816(ol[0], ol[1], ol[2], ol[3],
                         ap[kk][0], ap[kk][1], ap[kk][2], ap[kk][3], ONES2, ONES2);

            #pragma unroll
            for (int kk = 0; kk < 2; kk++) {
                const int lrow = cc * 32 + kk * 16 + (lane & 7) + ((lane >> 3) & 1) * 8;
                #pragma unroll
                for (int dh = 0; dh < 2; dh++) {
                    const int lcol = dh * 16 + ((lane >> 4) & 1) * 8;
                    uint32_t bv0, bv1, bv2, bv3;
                    uint32_t addr = smem_u32(&Vs[s * KV_STG + lrow * PAD + lcol]);
                    LDMX4T(bv0, bv1, bv2, bv3, addr);
                    MMA16816(o[2*dh  ][0], o[2*dh  ][1], o[2*dh  ][2], o[2*dh  ][3],
                             ap[kk][0], ap[kk][1], ap[kk][2], ap[kk][3], bv0, bv1);
                    MMA16816(o[2*dh+1][0], o[2*dh+1][1], o[2*dh+1][2], o[2*dh+1][3],
                             ap[kk][0], ap[kk][1], ap[kk][2], ap[kk][3], bv2, bv3);
                }
            }
        }
    }

    const float inv0 = 1.f / ol[0], inv1 = 1.f / ol[2];
    const int qrow0 = r0 + 16 * warp + g;
    const int qrow1 = qrow0 + 8;
    #pragma unroll
    for (int nd = 0; nd < 4; nd++) {
        const int col = h * DKH + nd * 8 + 2 * tg;
        *(__half2*)(XO + (size_t)bt * SEQ * DM + (size_t)qrow0 * DM + col) =
            __floats2half2_rn(o[nd][0] * inv0, o[nd][1] * inv0);
        *(__half2*)(XO + (size_t)bt * SEQ * DM + (size_t)qrow1 * DM + col) =
            __floats2half2_rn(o[nd][2] * inv1, o[nd][3] * inv1);
    }
}

// ---------------------------------------------------------------------------
// Reduce vpart partials -> fp16 mean vector per bt (done ONCE).
// ---------------------------------------------------------------------------
__global__ void vreduce_kernel(const float* __restrict__ vpart,
                               __half* __restrict__ meanh) {
    const int bt = blockIdx.x;
    const int d  = threadIdx.x;
    float tot = 0.f;
    #pragma unroll
    for (int p = 0; p < 8; p++) tot += vpart[(bt * 8 + p) * DM + d];
    meanh[bt * DM + d] = __float2half_rn(tot * (1.0f / SEQ));
}

// ---------------------------------------------------------------------------
extern "C" void kernel_launch(void* const* d_in, const int* in_sizes, int n_in,
                              void* d_out, int out_size) {
    const float* query = (const float*)d_in[0];
    const float* key   = (const float*)d_in[1];
    const float* value = (const float*)d_in[2];
    const int*   mask  = (const int*)  d_in[3];
    const float* Wq    = (const float*)d_in[4];
    const float* bq    = (const float*)d_in[5];
    const float* Wk    = (const float*)d_in[6];
    const float* bk    = (const float*)d_in[7];
    const float* Wv    = (const float*)d_in[8];
    const float* bv    = (const float*)d_in[9];
    const float* Wo    = (const float*)d_in[10];
    const float* bo    = (const float*)d_in[11];
    float* out = (float*)d_out;

    __half *qh, *kh, *vh, *xh, *whq, *whk, *whv, *who, *mh;
    float *vpa;
    cudaGetSymbolAddress((void**)&qh,  g_qh);
    cudaGetSymbolAddress((void**)&kh,  g_kh);
    cudaGetSymbolAddress((void**)&vh,  g_vh);
    cudaGetSymbolAddress((void**)&xh,  g_xh);
    cudaGetSymbolAddress((void**)&whq, g_whq);
    cudaGetSymbolAddress((void**)&whk, g_whk);
    cudaGetSymbolAddress((void**)&whv, g_whv);
    cudaGetSymbolAddress((void**)&who, g_who);
    cudaGetSymbolAddress((void**)&mh,  g_meanh);
    cudaGetSymbolAddress((void**)&vpa, g_vpart);

    // 1/sqrt(32) * log2(e): scores in log2 domain for exp2 softmax
    const float qscale = 0.25501500282705536f;

    wconv_kernel<<<dim3(64, 4), 256>>>(Wq, Wk, Wv, Wo, whq, whk, whv, who);

    dim3 ggrid(DM / 128, BTS / 128, 3);   // (2, 128, 3)
    gemm_qkv_kernel<<<ggrid, 256>>>(query, key, value, whq, whk, whv,
                                    bq, bk, bv, qh, kh, vh, qscale);

    dim3 agrid(SEQ / 128, NH + 1, NBT);   // (8, 9, 16): y==8 -> vmean
    attn_vmean_kernel<<<agrid, 256>>>(qh, kh, vh, mask, xh, vpa);

    vreduce_kernel<<<NBT, 256>>>(vpa, mh);

    dim3 ogrid(DM / 128, BTS / 128);
    gemm_out_kernel<<<ogrid, 256>>>(xh, who, bo, out, mask, mh);
}

// round 17
// speedup vs baseline: 1.3460x; 1.3460x over previous
#include <cuda_runtime.h>
#include <cuda_fp16.h>
#include <cstdint>

#define BTS   16384      // B*T*S
#define SEQ   1024
#define DM    256
#define NBT   16
#define NH    8
#define DKH   32

// Scratch (device globals — no allocation allowed)
__device__ __half g_qh [BTS * DM];
__device__ __half g_kh [BTS * DM];
__device__ __half g_vh [BTS * DM];
__device__ __half g_xh [BTS * DM];
__device__ __half g_whq[DM * DM];
__device__ __half g_whk[DM * DM];
__device__ __half g_whv[DM * DM];
__device__ __half g_who[DM * DM];
__device__ float  g_vpart[NBT * 8 * DM];

__device__ __forceinline__ uint32_t smem_u32(const void* p) {
    return (uint32_t)__cvta_generic_to_shared(p);
}

// PDL: wait for programmatic-launch predecessor grid (memory visibility).
#define GDC_WAIT() asm volatile("griddepcontrol.wait;" ::: "memory")

#define LDMX4(r0,r1,r2,r3,addr) \
    asm volatile("ldmatrix.sync.aligned.m8n8.x4.shared.b16 {%0,%1,%2,%3}, [%4];" \
        : "=r"(r0),"=r"(r1),"=r"(r2),"=r"(r3) : "r"(addr))

#define LDMX4T(r0,r1,r2,r3,addr) \
    asm volatile("ldmatrix.sync.aligned.m8n8.x4.trans.shared.b16 {%0,%1,%2,%3}, [%4];" \
        : "=r"(r0),"=r"(r1),"=r"(r2),"=r"(r3) : "r"(addr))

#define MMA16816(c0,c1,c2,c3,a0,a1,a2,a3,b0,b1) \
    asm volatile("mma.sync.aligned.m16n8k16.row.col.f32.f16.f16.f32 " \
        "{%0,%1,%2,%3}, {%4,%5,%6,%7}, {%8,%9}, {%0,%1,%2,%3};" \
        : "+f"(c0),"+f"(c1),"+f"(c2),"+f"(c3) \
        : "r"(a0),"r"(a1),"r"(a2),"r"(a3), "r"(b0),"r"(b1))

#define EX2F16X2(r) \
    asm volatile("ex2.approx.f16x2 %0, %0;" : "+r"(r))

#define CP16(dst, src) \
    asm volatile("cp.async.cg.shared.global [%0], [%1], 16;" :: "r"(dst), "l"(src))
#define CP_COMMIT()  asm volatile("cp.async.commit_group;")
#define CP_WAIT1()   asm volatile("cp.async.wait_group 1;")

// ---------------------------------------------------------------------------
// Weight fp32 -> fp16 (4 matrices 256x256)
// ---------------------------------------------------------------------------
__global__ void wconv_kernel(const float* __restrict__ s0, const float* __restrict__ s1,
                             const float* __restrict__ s2, const float* __restrict__ s3,
                             __half* __restrict__ d0, __half* __restrict__ d1,
                             __half* __restrict__ d2, __half* __restrict__ d3) {
    const float* s; __half* d;
    switch (blockIdx.y) {
        case 0: s = s0; d = d0; break;
        case 1: s = s1; d = d1; break;
        case 2: s = s2; d = d2; break;
        default: s = s3; d = d3; break;
    }
    const int i = (blockIdx.x * 256 + threadIdx.x) * 4;
    float4 v = *(const float4*)(s + i);
    *(__half2*)(d + i)     = __floats2half2_rn(v.x, v.y);
    *(__half2*)(d + i + 2) = __floats2half2_rn(v.z, v.w);
}

// ---------------------------------------------------------------------------
// QKV GEMM reading fp32 A directly (round-12/14 proven form).
// ---------------------------------------------------------------------------
#define PADG 40
#define STG_H (128 * PADG)

__global__ void __launch_bounds__(256, 2)
gemm_qkv_kernel(const float* __restrict__ A0, const float* __restrict__ A1,
                const float* __restrict__ A2,
                const __half* __restrict__ W0, const __half* __restrict__ W1,
                const __half* __restrict__ W2,
                const float* __restrict__ b0, const float* __restrict__ b1,
                const float* __restrict__ b2,
                __half* __restrict__ C0, __half* __restrict__ C1,
                __half* __restrict__ C2, float qscale) {
    __shared__ __half As[2 * STG_H];
    __shared__ __half Bs[3 * STG_H];

    GDC_WAIT();

    const float* A; const __half* W; const float* bias; __half* C; float scale;
    switch (blockIdx.z) {
        case 0:  A = A0; W = W0; bias = b0; C = C0; scale = qscale; break;
        case 1:  A = A1; W = W1; bias = b1; C = C1; scale = 1.0f;   break;
        default: A = A2; W = W2; bias = b2; C = C2; scale = 1.0f;   break;
    }

    const int tid    = threadIdx.x;
    const int warp   = tid >> 5;
    const int lane   = tid & 31;
    const int warp_m = warp >> 2;
    const int warp_n = warp & 3;
    const int m0     = blockIdx.y * 128;
    const int n0     = blockIdx.x * 128;
    const int g      = lane >> 2;
    const int tg     = lane & 3;

    const int arow  = tid >> 1;
    const int acol  = (tid & 1) * 16;
    const float* Abase = A + (size_t)(m0 + arow) * DM + acol;

    uint4 areg[2];
    auto aload = [&](int k0) {
        #pragma unroll
        for (int i = 0; i < 2; i++) {
            float4 f0 = *(const float4*)(Abase + k0 + i * 8);
            float4 f1 = *(const float4*)(Abase + k0 + i * 8 + 4);
            __half2 h0 = __floats2half2_rn(f0.x, f0.y);
            __half2 h1 = __floats2half2_rn(f0.z, f0.w);
            __half2 h2 = __floats2half2_rn(f1.x, f1.y);
            __half2 h3 = __floats2half2_rn(f1.z, f1.w);
            areg[i].x = *(uint32_t*)&h0; areg[i].y = *(uint32_t*)&h1;
            areg[i].z = *(uint32_t*)&h2; areg[i].w = *(uint32_t*)&h3;
        }
    };
    auto asts = [&](int buf) {
        *(uint4*)&As[buf * STG_H + arow * PADG + acol]     = areg[0];
        *(uint4*)&As[buf * STG_H + arow * PADG + acol + 8] = areg[1];
    };
    auto bcopy = [&](int stg, int k0) {
        #pragma unroll
        for (int u = tid; u < 512; u += 256) {
            const int row = u >> 2, seg = u & 3;
            CP16(smem_u32(&Bs[stg * STG_H + row * PADG + seg * 8]),
                 W + (size_t)(n0 + row) * DM + k0 + seg * 8);
        }
    };

    float c[4][4][4] = {};

    aload(0);
    bcopy(0, 0);  CP_COMMIT();
    bcopy(1, 32); CP_COMMIT();
    asts(0);
    aload(32);
    CP_WAIT1();
    __syncthreads();

    #pragma unroll
    for (int step = 0; step < 8; step++) {
        const int sa = step & 1;
        const int sb = step % 3;

        if (step < 7) asts((step + 1) & 1);
        if (step < 6) aload((step + 2) * 32);
        if (step + 2 < 8) bcopy((step + 2) % 3, (step + 2) * 32);
        CP_COMMIT();

        uint32_t bb[4][4];
        #pragma unroll
        for (int ni = 0; ni < 4; ni++) {
            const int lrow = warp_n * 32 + ni * 8 + (lane & 7);
            const int lcol = (lane >> 3) * 8;
            uint32_t addr = smem_u32(&Bs[sb * STG_H + lrow * PADG + lcol]);
            LDMX4(bb[ni][0], bb[ni][1], bb[ni][2], bb[ni][3], addr);
        }

        #pragma unroll
        for (int kh = 0; kh < 2; kh++) {
            uint32_t aa[4][4];
            const int lcol = kh * 16 + ((lane >> 4) & 1) * 8;
            #pragma unroll
            for (int mi = 0; mi < 4; mi++) {
                const int lrow = warp_m * 64 + mi * 16 + (lane & 7) + ((lane >> 3) & 1) * 8;
                uint32_t addr = smem_u32(&As[sa * STG_H + lrow * PADG + lcol]);
                LDMX4(aa[mi][0], aa[mi][1], aa[mi][2], aa[mi][3], addr);
            }
            #pragma unroll
            for (int mi = 0; mi < 4; mi++)
                #pragma unroll
                for (int ni = 0; ni < 4; ni++)
                    MMA16816(c[mi][ni][0], c[mi][ni][1], c[mi][ni][2], c[mi][ni][3],
                             aa[mi][0], aa[mi][1], aa[mi][2], aa[mi][3],
                             bb[ni][kh * 2], bb[ni][kh * 2 + 1]);
        }

        CP_WAIT1();
        __syncthreads();
    }

    #pragma unroll
    for (int mi = 0; mi < 4; mi++) {
        const int row0 = m0 + warp_m * 64 + mi * 16 + g;
        const int row1 = row0 + 8;
        #pragma unroll
        for (int ni = 0; ni < 4; ni++) {
            const int col = n0 + warp_n * 32 + ni * 8 + 2 * tg;
            const float bb0 = bias[col], bb1 = bias[col + 1];
            *(__half2*)(C + (size_t)row0 * DM + col) =
                __floats2half2_rn((c[mi][ni][0] + bb0) * scale, (c[mi][ni][1] + bb1) * scale);
            *(__half2*)(C + (size_t)row1 * DM + col) =
                __floats2half2_rn((c[mi][ni][2] + bb0) * scale, (c[mi][ni][3] + bb1) * scale);
        }
    }
}

// ---------------------------------------------------------------------------
// Output GEMM (fp16 A, fp16 W, fp32 out): 3-buffer cp.async ring.
// ---------------------------------------------------------------------------
__global__ void __launch_bounds__(256, 2)
gemm_out_kernel(const __half* __restrict__ A, const __half* __restrict__ W,
                const float* __restrict__ bias, float* __restrict__ C) {
    __shared__ __half As[3 * STG_H];
    __shared__ __half Bs[3 * STG_H];

    GDC_WAIT();

    const int tid    = threadIdx.x;
    const int warp   = tid >> 5;
    const int lane   = tid & 31;
    const int warp_m = warp >> 2;
    const int warp_n = warp & 3;
    const int m0     = blockIdx.y * 128;
    const int n0     = blockIdx.x * 128;
    const int g      = lane >> 2;
    const int tg     = lane & 3;

    auto stage_copy = [&](int s, int k0) {
        #pragma unroll
        for (int u = tid; u < 512; u += 256) {
            const int row = u >> 2, seg = u & 3;
            CP16(smem_u32(&As[s * STG_H + row * PADG + seg * 8]),
                 A + (size_t)(m0 + row) * DM + k0 + seg * 8);
            CP16(smem_u32(&Bs[s * STG_H + row * PADG + seg * 8]),
                 W + (size_t)(n0 + row) * DM + k0 + seg * 8);
        }
        CP_COMMIT();
    };

    float c[4][4][4] = {};
    stage_copy(0, 0);
    stage_copy(1, 32);

    #pragma unroll
    for (int step = 0; step < 8; step++) {
        const int s = step % 3;
        CP_WAIT1();
        __syncthreads();

        const int kn = (step + 2 < 8) ? (step + 2) * 32 : 224;
        stage_copy((step + 2) % 3, kn);

        uint32_t bb[4][4];
        #pragma unroll
        for (int ni = 0; ni < 4; ni++) {
            const int lrow = warp_n * 32 + ni * 8 + (lane & 7);
            const int lcol = (lane >> 3) * 8;
            uint32_t addr = smem_u32(&Bs[s * STG_H + lrow * PADG + lcol]);
            LDMX4(bb[ni][0], bb[ni][1], bb[ni][2], bb[ni][3], addr);
        }
        #pragma unroll
        for (int kh = 0; kh < 2; kh++) {
            uint32_t aa[4][4];
            const int lcol = kh * 16 + ((lane >> 4) & 1) * 8;
            #pragma unroll
            for (int mi = 0; mi < 4; mi++) {
                const int lrow = warp_m * 64 + mi * 16 + (lane & 7) + ((lane >> 3) & 1) * 8;
                uint32_t addr = smem_u32(&As[s * STG_H + lrow * PADG + lcol]);
                LDMX4(aa[mi][0], aa[mi][1], aa[mi][2], aa[mi][3], addr);
            }
            #pragma unroll
            for (int mi = 0; mi < 4; mi++)
                #pragma unroll
                for (int ni = 0; ni < 4; ni++)
                    MMA16816(c[mi][ni][0], c[mi][ni][1], c[mi][ni][2], c[mi][ni][3],
                             aa[mi][0], aa[mi][1], aa[mi][2], aa[mi][3],
                             bb[ni][kh * 2], bb[ni][kh * 2 + 1]);
        }
    }

    #pragma unroll
    for (int mi = 0; mi < 4; mi++) {
        const int row0 = m0 + warp_m * 64 + mi * 16 + g;
        const int row1 = row0 + 8;
        #pragma unroll
        for (int ni = 0; ni < 4; ni++) {
            const int col = n0 + warp_n * 32 + ni * 8 + 2 * tg;
            const float b0 = bias[col], b1 = bias[col + 1];
            *(float2*)(C + (size_t)row0 * DM + col) = make_float2(c[mi][ni][0] + b0, c[mi][ni][1] + b1);
            *(float2*)(C + (size_t)row1 * DM + col) = make_float2(c[mi][ni][2] + b0, c[mi][ni][3] + b1);
        }
    }
}

// ---------------------------------------------------------------------------
// Flash attention (log2-domain single-pass softmax, 32-key chunks) FUSED with
// V column partial sums: blockIdx.y == NH does vmean for (bt, seg=blockIdx.x).
// ---------------------------------------------------------------------------
#define PAD 40
#define KV_STG (64 * PAD)

__global__ void __launch_bounds__(256, 3)
attn_vmean_kernel(const __half* __restrict__ Qh,
                  const __half* __restrict__ Kh,
                  const __half* __restrict__ Vh,
                  const int*    __restrict__ mask,
                  __half* __restrict__ XO,
                  float* __restrict__ vpart) {
    __shared__ __half Qs[128 * PAD];
    __shared__ __half Ks[3 * KV_STG];
    __shared__ __half Vs[3 * KV_STG];

    GDC_WAIT();

    const int bt = blockIdx.z;

    // ---- vmean blocks (memory-bound; overlap with tensor-bound attn CTAs) ----
    if (blockIdx.y == NH) {
        const int seg = blockIdx.x;
        const int d   = threadIdx.x;
        const size_t b0 = (size_t)bt * SEQ * DM;
        float sum = 0.f;
        const int s0 = seg * 128;
        #pragma unroll 4
        for (int s = s0; s < s0 + 128; s++)
            sum += __half2float(Vh[b0 + (size_t)s * DM + d]);
        vpart[(bt * 8 + seg) * DM + d] = sum;
        return;
    }

    const int h   = blockIdx.y;
    const int r0  = blockIdx.x * 128;
    const int len = mask[bt];
    if (r0 >= len) return;

    const int tid  = threadIdx.x;
    const int warp = tid >> 5;
    const int lane = tid & 31;
    const int g    = lane >> 2;
    const int tg   = lane & 3;

    const size_t base = (size_t)bt * SEQ * DM + (size_t)h * DKH;

    const int crow = tid >> 2, cseg = tid & 3;
    auto copy_kv = [&](int stg, int t0) {
        const size_t src = base + (size_t)(t0 + crow) * DM + cseg * 8;
        CP16(smem_u32(&Ks[stg * KV_STG + crow * PAD + cseg * 8]), Kh + src);
        CP16(smem_u32(&Vs[stg * KV_STG + crow * PAD + cseg * 8]), Vh + src);
        CP_COMMIT();
    };

    const int ntile = (len + 63) >> 6;
    copy_kv(0, 0);
    copy_kv(1, (ntile > 1) ? 64 : 0);

    #pragma unroll
    for (int u = tid; u < 512; u += 256) {
        int row = u >> 2, ch = u & 3;
        *(uint4*)&Qs[row * PAD + ch * 8] =
            *(const uint4*)(Qh + base + (size_t)(r0 + row) * DM + ch * 8);
    }
    __syncthreads();

    uint32_t aq[2][4];
    {
        const int lrow = 16 * warp + (lane & 7) + ((lane >> 3) & 1) * 8;
        #pragma unroll
        for (int kh = 0; kh < 2; kh++) {
            const int lcol = kh * 16 + ((lane >> 4) & 1) * 8;
            uint32_t addr = smem_u32(&Qs[lrow * PAD + lcol]);
            LDMX4(aq[kh][0], aq[kh][1], aq[kh][2], aq[kh][3], addr);
        }
    }

    const uint32_t ONES2 = 0x3C003C00u;
    float ol[4] = {};
    float o[4][4] = {};

    for (int i = 0; i < ntile; i++) {
        const int s  = i % 3;
        const int t0 = i * 64;
        CP_WAIT1();
        __syncthreads();

        int tn = (i + 2) * 64;
        if (tn > SEQ - 64) tn = SEQ - 64;
        copy_kv((i + 2) % 3, tn);

        #pragma unroll
        for (int cc = 0; cc < 2; cc++) {
            float c[4][4];
            #pragma unroll
            for (int n = 0; n < 4; n++) { c[n][0]=0.f; c[n][1]=0.f; c[n][2]=0.f; c[n][3]=0.f; }

            #pragma unroll
            for (int n = 0; n < 4; n++) {
                uint32_t bk0, bk1, bk2, bk3;
                const int lrow = cc * 32 + n * 8 + (lane & 7);
                const int lcol = (lane >> 3) * 8;
                uint32_t addr = smem_u32(&Ks[s * KV_STG + lrow * PAD + lcol]);
                LDMX4(bk0, bk1, bk2, bk3, addr);
                MMA16816(c[n][0], c[n][1], c[n][2], c[n][3],
                         aq[0][0], aq[0][1], aq[0][2], aq[0][3], bk0, bk1);
                MMA16816(c[n][0], c[n][1], c[n][2], c[n][3],
                         aq[1][0], aq[1][1], aq[1][2], aq[1][3], bk2, bk3);
            }

            if (t0 + cc * 32 + 32 > len) {
                #pragma unroll
                for (int n = 0; n < 4; n++) {
                    const int col0 = t0 + cc * 32 + n * 8 + 2 * tg;
                    if (col0     >= len) { c[n][0] = -1e10f; c[n][2] = -1e10f; }
                    if (col0 + 1 >= len) { c[n][1] = -1e10f; c[n][3] = -1e10f; }
                }
            }

            uint32_t ap[2][4];
            #pragma unroll
            for (int kk = 0; kk < 2; kk++) {
                __half2 t;
                t = __floats2half2_rn(c[2*kk  ][0], c[2*kk  ][1]); ap[kk][0] = *(uint32_t*)&t;
                t = __floats2half2_rn(c[2*kk  ][2], c[2*kk  ][3]); ap[kk][1] = *(uint32_t*)&t;
                t = __floats2half2_rn(c[2*kk+1][0], c[2*kk+1][1]); ap[kk][2] = *(uint32_t*)&t;
                t = __floats2half2_rn(c[2*kk+1][2], c[2*kk+1][3]); ap[kk][3] = *(uint32_t*)&t;
                EX2F16X2(ap[kk][0]); EX2F16X2(ap[kk][1]);
                EX2F16X2(ap[kk][2]); EX2F16X2(ap[kk][3]);
            }

            #pragma unroll
            for (int kk = 0; kk < 2; kk++)
                MMA16816(ol[0], ol[1], ol[2], ol[3],
                         ap[kk][0], ap[kk][1], ap[kk][2], ap[kk][3], ONES2, ONES2);

            #pragma unroll
            for (int kk = 0; kk < 2; kk++) {
                const int lrow = cc * 32 + kk * 16 + (lane & 7) + ((lane >> 3) & 1) * 8;
                #pragma unroll
                for (int dh = 0; dh < 2; dh++) {
                    const int lcol = dh * 16 + ((lane >> 4) & 1) * 8;
                    uint32_t bv0, bv1, bv2, bv3;
                    uint32_t addr = smem_u32(&Vs[s * KV_STG + lrow * PAD + lcol]);
                    LDMX4T(bv0, bv1, bv2, bv3, addr);
                    MMA16816(o[2*dh  ][0], o[2*dh  ][1], o[2*dh  ][2], o[2*dh  ][3],
                             ap[kk][0], ap[kk][1], ap[kk][2], ap[kk][3], bv0, bv1);
                    MMA16816(o[2*dh+1][0], o[2*dh+1][1], o[2*dh+1][2], o[2*dh+1][3],
                             ap[kk][0], ap[kk][1], ap[kk][2], ap[kk][3], bv2, bv3);
                }
            }
        }
    }

    const float inv0 = 1.f / ol[0], inv1 = 1.f / ol[2];
    const int qrow0 = r0 + 16 * warp + g;
    const int qrow1 = qrow0 + 8;
    #pragma unroll
    for (int nd = 0; nd < 4; nd++) {
        const int col = h * DKH + nd * 8 + 2 * tg;
        *(__half2*)(XO + (size_t)bt * SEQ * DM + (size_t)qrow0 * DM + col) =
            __floats2half2_rn(o[nd][0] * inv0, o[nd][1] * inv0);
        *(__half2*)(XO + (size_t)bt * SEQ * DM + (size_t)qrow1 * DM + col) =
            __floats2half2_rn(o[nd][2] * inv1, o[nd][3] * inv1);
    }
}

// ---------------------------------------------------------------------------
// Fill rows q >= len with mean(V). grid (NBT, 64): 16-row segments.
// ---------------------------------------------------------------------------
__global__ void fill_invalid_kernel(const float* __restrict__ vpart,
                                    const int* __restrict__ mask,
                                    __half* __restrict__ XO) {
    GDC_WAIT();
    const int bt  = blockIdx.x;
    const int seg = blockIdx.y;
    const int d   = threadIdx.x;
    const int len = mask[bt];
    const int s0  = seg * 16;
    const int send = s0 + 16;
    if (send <= len) return;
    float tot = 0.f;
    #pragma unroll
    for (int p = 0; p < 8; p++) tot += vpart[(bt * 8 + p) * DM + d];
    const __half mean = __float2half_rn(tot * (1.0f / SEQ));
    const size_t b0 = (size_t)bt * SEQ * DM;
    for (int s = (s0 > len ? s0 : len); s < send; s++)
        XO[b0 + (size_t)s * DM + d] = mean;
}

// ---------------------------------------------------------------------------
// Host-side PDL launch helper
// ---------------------------------------------------------------------------
template <typename K, typename... Args>
static inline void launch_pdl(dim3 grid, dim3 block, K kernel, Args... args) {
    cudaLaunchConfig_t cfg = {};
    cfg.gridDim  = grid;
    cfg.blockDim = block;
    cudaLaunchAttribute attr[1];
    attr[0].id = cudaLaunchAttributeProgrammaticStreamSerialization;
    attr[0].val.programmaticStreamSerializationAllowed = 1;
    cfg.attrs    = attr;
    cfg.numAttrs = 1;
    cudaLaunchKernelEx(&cfg, kernel, args...);
}

// ---------------------------------------------------------------------------
extern "C" void kernel_launch(void* const* d_in, const int* in_sizes, int n_in,
                              void* d_out, int out_size) {
    const float* query = (const float*)d_in[0];
    const float* key   = (const float*)d_in[1];
    const float* value = (const float*)d_in[2];
    const int*   mask  = (const int*)  d_in[3];
    const float* Wq    = (const float*)d_in[4];
    const float* bq    = (const float*)d_in[5];
    const float* Wk    = (const float*)d_in[6];
    const float* bk    = (const float*)d_in[7];
    const float* Wv    = (const float*)d_in[8];
    const float* bv    = (const float*)d_in[9];
    const float* Wo    = (const float*)d_in[10];
    const float* bo    = (const float*)d_in[11];
    float* out = (float*)d_out;

    __half *qh, *kh, *vh, *xh, *whq, *whk, *whv, *who;
    float *vpa;
    cudaGetSymbolAddress((void**)&qh,  g_qh);
    cudaGetSymbolAddress((void**)&kh,  g_kh);
    cudaGetSymbolAddress((void**)&vh,  g_vh);
    cudaGetSymbolAddress((void**)&xh,  g_xh);
    cudaGetSymbolAddress((void**)&whq, g_whq);
    cudaGetSymbolAddress((void**)&whk, g_whk);
    cudaGetSymbolAddress((void**)&whv, g_whv);
    cudaGetSymbolAddress((void**)&who, g_who);
    cudaGetSymbolAddress((void**)&vpa, g_vpart);

    // 1/sqrt(32) * log2(e): scores in log2 domain for exp2 softmax
    const float qscale = 0.25501500282705536f;

    wconv_kernel<<<dim3(64, 4), 256>>>(Wq, Wk, Wv, Wo, whq, whk, whv, who);

    launch_pdl(dim3(DM / 128, BTS / 128, 3), dim3(256),
               gemm_qkv_kernel, query, key, value, whq, whk, whv,
               bq, bk, bv, qh, kh, vh, qscale);

    launch_pdl(dim3(SEQ / 128, NH + 1, NBT), dim3(256),
               attn_vmean_kernel,
               (const __half*)qh, (const __half*)kh, (const __half*)vh,
               mask, xh, vpa);

    launch_pdl(dim3(NBT, 64), dim3(256),
               fill_invalid_kernel, (const float*)vpa, mask, xh);

    launch_pdl(dim3(DM / 128, BTS / 128), dim3(256),
               gemm_out_kernel, (const __half*)xh, (const __half*)who, bo, out);
}